// round 6
// baseline (speedup 1.0000x reference)
#include <cuda_runtime.h>
#include <cstdint>

#define NTOT 500000
#define CT 64
#define THREADS 512
#define NTILES ((NTOT + CT - 1) / CT)   // 7813

// smem layout (float offsets)
#define OFF_WT 0        // [128 k][128 n], n ^ ((k&3)<<3)
#define OFF_WG 16384
#define OFF_X  32768    // [64 m][128 k], k ^ ((m&7)<<2)
#define OFF_M  40960    // [128 b][64 k] int, k ^ ((b&7)<<2)
#define OFF_Y  49152    // [64 m][128 n], n ^ (((m&3)<<3)|((m&4)>>2))
#define OFF_BT 57344
#define OFF_BG 57472
#define SMEM_FLOATS 57600
#define SMEM_BYTES (SMEM_FLOATS * 4)    // 230400 <= 232448

__device__ __forceinline__ float cvt_tf32_f(float x) {
    uint32_t u; asm("cvt.rna.tf32.f32 %0, %1;" : "=r"(u) : "f"(x));
    return __uint_as_float(u);
}
__device__ __forceinline__ void mma8(float* c,
                                     uint32_t a0, uint32_t a1, uint32_t a2, uint32_t a3,
                                     uint32_t b0, uint32_t b1) {
    asm volatile(
        "mma.sync.aligned.m16n8k8.row.col.f32.tf32.tf32.f32 "
        "{%0,%1,%2,%3}, {%4,%5,%6,%7}, {%8,%9}, {%0,%1,%2,%3};"
        : "+f"(c[0]), "+f"(c[1]), "+f"(c[2]), "+f"(c[3])
        : "r"(a0), "r"(a1), "r"(a2), "r"(a3), "r"(b0), "r"(b1));
}
__device__ __forceinline__ void cp16(uint32_t saddr, const void* g, int szbytes) {
    asm volatile("cp.async.cg.shared.global [%0], [%1], 16, %2;"
                 :: "r"(saddr), "l"(g), "r"(szbytes));
}
#define CP_COMMIT() asm volatile("cp.async.commit_group;")
#define CP_WAIT0()  asm volatile("cp.async.wait_group 0;")
#define BAR_SYNC(id) asm volatile("bar.sync %0, %1;" :: "r"(id), "r"(512) : "memory")
#define BAR_ARRIVE(id) asm volatile("bar.arrive %0, %1;" :: "r"(id), "r"(512) : "memory")
#define BAR_HALF(id) asm volatile("bar.sync %0, %1;" :: "r"(id), "r"(256) : "memory")

extern "C" __global__ void zero_out_kernel(float* __restrict__ out) {
    int i = blockIdx.x * blockDim.x + threadIdx.x;
    if (i < 128 * 128) out[i] = 0.0f;
}

extern "C" __global__ void __launch_bounds__(THREADS, 1)
agg_kernel(const float* __restrict__ nodes, const int* __restrict__ masks,
           const float* __restrict__ Wt, const float* __restrict__ bt,
           const float* __restrict__ Wg, const float* __restrict__ bg,
           float* __restrict__ out) {
    extern __shared__ float sm[];
    float* sWt = sm + OFF_WT;
    float* sWg = sm + OFF_WG;
    float* sX  = sm + OFF_X;
    int*   sM  = (int*)(sm + OFF_M);
    float* sY  = sm + OFF_Y;
    float* sBt = sm + OFF_BT;
    float* sBg = sm + OFF_BG;

    const uint32_t smem_u32 = (uint32_t)__cvta_generic_to_shared(sm);
    const uint32_t sx_u32 = smem_u32 + OFF_X * 4;
    const uint32_t sm_u32 = smem_u32 + OFF_M * 4;

    const int tid  = threadIdx.x;
    const int warp = tid >> 5;
    const int lane = tid & 31;
    const int tg   = lane & 3;
    const int gid  = lane >> 2;
    const int stride = gridDim.x;

    // ---- role-specific prologue streams (issued before W LDGs for overlap) ----
    if (warp < 8) {
        const int atid = tid;                    // 0..255
        if (blockIdx.x < NTILES) {
            const int n0 = blockIdx.x * CT;
#pragma unroll
            for (int p = 0; p < 8; p++) {
                int id = atid + 256 * p;
                int row = id >> 5, ch = id & 31;
                int n = n0 + row;
                cp16(sx_u32 + (((row << 7) + ((ch ^ (row & 7)) << 2)) << 2),
                     nodes + (size_t)(n < NTOT ? n : 0) * 128 + ch * 4, n < NTOT ? 16 : 0);
            }
        }
        CP_COMMIT();
    } else {
        const int btid = tid - 256;              // 0..255
        if (blockIdx.x < NTILES) {
            const int n0 = blockIdx.x * CT;
#pragma unroll
            for (int p = 0; p < 8; p++) {
                int id = btid + 256 * p;
                int b = id >> 4, ch = id & 15;
                int ok = (n0 + ch * 4) < NTOT;
                cp16(sm_u32 + (((b << 6) + ((ch ^ (b & 7)) << 2)) << 2),
                     masks + (size_t)b * NTOT + (ok ? n0 + ch * 4 : 0), ok ? 16 : 0);
            }
        }
        CP_COMMIT();
    }

    // ---- W + bias (once, all threads), W pre-rounded rna ----
    for (int i = tid; i < 128 * 128; i += THREADS) {
        int k = i >> 7, n = i & 127;
        int idx = (k << 7) + (n ^ ((k & 3) << 3));
        sWt[idx] = cvt_tf32_f(Wt[i]);
        sWg[idx] = cvt_tf32_f(Wg[i]);
    }
    if (tid < 128) { sBt[tid] = bt[tid]; sBg[tid] = bg[tid]; }
    __syncthreads();

    if (warp < 8) {
        // ================= producer: GEMM + epilogue =================
        const int wm = warp & 1;                 // m-base 32*wm
        const int wq = warp >> 1;                // n-base 32*wq
        const int atid = tid;
        const int xsw = gid << 2;
        const int swc = ((gid & 3) << 3) | ((gid & 4) >> 2);

        int it = 0;
        for (int t = blockIdx.x; t < NTILES; t += stride, ++it) {
            CP_WAIT0();
            BAR_HALF(3);                         // X(t) visible to all A-warps

            float aD[2][4][4], aG[2][4][4];
#pragma unroll
            for (int s = 0; s < 2; s++)
#pragma unroll
                for (int j = 0; j < 4; j++)
#pragma unroll
                    for (int r = 0; r < 4; r++) { aD[s][j][r] = 0.0f; aG[s][j][r] = 0.0f; }

#pragma unroll 2
            for (int ks = 0; ks < 16; ks++) {
                const int k0 = ks * 8 + tg;
                const int r0 = ((wm << 5) + gid) << 7;
                uint32_t a0 = __float_as_uint(sX[r0 + (k0 ^ xsw)]);
                uint32_t a1 = __float_as_uint(sX[r0 + (8 << 7) + (k0 ^ xsw)]);
                uint32_t a2 = __float_as_uint(sX[r0 + ((k0 + 4) ^ xsw)]);
                uint32_t a3 = __float_as_uint(sX[r0 + (8 << 7) + ((k0 + 4) ^ xsw)]);
                uint32_t a4 = __float_as_uint(sX[r0 + (16 << 7) + (k0 ^ xsw)]);
                uint32_t a5 = __float_as_uint(sX[r0 + (24 << 7) + (k0 ^ xsw)]);
                uint32_t a6 = __float_as_uint(sX[r0 + (16 << 7) + ((k0 + 4) ^ xsw)]);
                uint32_t a7 = __float_as_uint(sX[r0 + (24 << 7) + ((k0 + 4) ^ xsw)]);
                const int base0 = k0 << 7;
                const int base1 = (k0 + 4) << 7;
#pragma unroll
                for (int j = 0; j < 4; j++) {
                    const int cidx = ((wq << 5) + 8 * j + gid) ^ (tg << 3);
                    uint32_t d0 = __float_as_uint(sWt[base0 + cidx]);
                    uint32_t d1 = __float_as_uint(sWt[base1 + cidx]);
                    mma8(aD[0][j], a0, a1, a2, a3, d0, d1);
                    mma8(aD[1][j], a4, a5, a6, a7, d0, d1);
                    uint32_t g0 = __float_as_uint(sWg[base0 + cidx]);
                    uint32_t g1 = __float_as_uint(sWg[base1 + cidx]);
                    mma8(aG[0][j], a0, a1, a2, a3, g0, g1);
                    mma8(aG[1][j], a4, a5, a6, a7, g0, g1);
                }
            }
            BAR_HALF(3);                         // all A-warps done reading sX

            // prefetch X(t+stride) into the (now free) X buffer
            {
                const int tn = t + stride;
                if (tn < NTILES) {
                    const int nn0 = tn * CT;
#pragma unroll
                    for (int p = 0; p < 8; p++) {
                        int id = atid + 256 * p;
                        int row = id >> 5, ch = id & 31;
                        int n = nn0 + row;
                        cp16(sx_u32 + (((row << 7) + ((ch ^ (row & 7)) << 2)) << 2),
                             nodes + (size_t)(n < NTOT ? n : 0) * 128 + ch * 4,
                             n < NTOT ? 16 : 0);
                    }
                }
                CP_COMMIT();
            }

            if (it) BAR_SYNC(2);                 // B consumed Y(t-1)

            // epilogue: y = (d+bt)*sigmoid(g+bg), tf32-rounded -> sY
#pragma unroll
            for (int s = 0; s < 2; s++)
#pragma unroll
                for (int j = 0; j < 4; j++)
#pragma unroll
                    for (int r = 0; r < 4; r++) {
                        int r1 = r & 1, r2 = r >> 1;
                        int m = (wm << 5) + 16 * s + 8 * r2 + gid;
                        int n = (wq << 5) + 8 * j + 2 * tg + r1;
                        float d  = aD[s][j][r] + sBt[n];
                        float gl = aG[s][j][r] + sBg[n];
                        float y = d / (1.0f + __expf(-gl));
                        sY[(m << 7) + (n ^ swc)] = cvt_tf32_f(y);
                    }
            BAR_ARRIVE(1);                       // Y(t) ready
        }
        BAR_SYNC(2);                             // consume B's final arrive
    } else {
        // ================= consumer: pooling =================
        const int wb = warp - 8;
        const int pb = wb & 3;                   // b-base 32*pb
        const int pd = wb >> 2;                  // d-base 64*pd
        const int btid = tid - 256;
        const int msw = gid << 2;

        float pc[2][8][4];
#pragma unroll
        for (int s = 0; s < 2; s++)
#pragma unroll
            for (int j = 0; j < 8; j++)
#pragma unroll
                for (int r = 0; r < 4; r++) pc[s][j][r] = 0.0f;

        for (int t = blockIdx.x; t < NTILES; t += stride) {
            CP_WAIT0();
            BAR_HALF(4);                         // M(t) visible to all B-warps
            BAR_SYNC(1);                         // Y(t) ready

            const int brow0 = (pb << 5) + gid;
#pragma unroll 4
            for (int ks = 0; ks < 8; ks++) {
                const int kk = ks * 8 + tg;
                uint32_t m0 = __float_as_uint((float)sM[(brow0 << 6)        + (kk ^ msw)]);
                uint32_t m1 = __float_as_uint((float)sM[((brow0 + 8) << 6)  + (kk ^ msw)]);
                uint32_t m2 = __float_as_uint((float)sM[(brow0 << 6)        + ((kk + 4) ^ msw)]);
                uint32_t m3 = __float_as_uint((float)sM[((brow0 + 8) << 6)  + ((kk + 4) ^ msw)]);
                uint32_t m4 = __float_as_uint((float)sM[((brow0 + 16) << 6) + (kk ^ msw)]);
                uint32_t m5 = __float_as_uint((float)sM[((brow0 + 24) << 6) + (kk ^ msw)]);
                uint32_t m6 = __float_as_uint((float)sM[((brow0 + 16) << 6) + ((kk + 4) ^ msw)]);
                uint32_t m7 = __float_as_uint((float)sM[((brow0 + 24) << 6) + ((kk + 4) ^ msw)]);
                const int yb0 = kk << 7;
                const int yb1 = (kk + 4) << 7;
                const int ysw0 = tg << 3;
                const int ysw1 = (tg << 3) | 1;
#pragma unroll
                for (int j = 0; j < 8; j++) {
                    const int d = (pd << 6) + 8 * j + gid;
                    uint32_t y0 = __float_as_uint(sY[yb0 + (d ^ ysw0)]);
                    uint32_t y1 = __float_as_uint(sY[yb1 + (d ^ ysw1)]);
                    mma8(pc[0][j], m0, m1, m2, m3, y0, y1);
                    mma8(pc[1][j], m4, m5, m6, m7, y0, y1);
                }
            }
            BAR_HALF(4);                         // all B-warps done with sM/sY
            BAR_ARRIVE(2);                       // Y/M consumed

            // prefetch M(t+stride)
            {
                const int tn = t + stride;
                if (tn < NTILES) {
                    const int nn0 = tn * CT;
#pragma unroll
                    for (int p = 0; p < 8; p++) {
                        int id = btid + 256 * p;
                        int b = id >> 4, ch = id & 15;
                        int ok = (nn0 + ch * 4) < NTOT;
                        cp16(sm_u32 + (((b << 6) + ((ch ^ (b & 7)) << 2)) << 2),
                             masks + (size_t)b * NTOT + (ok ? nn0 + ch * 4 : 0), ok ? 16 : 0);
                    }
                }
                CP_COMMIT();
            }
        }

        CP_WAIT0();
#pragma unroll
        for (int s = 0; s < 2; s++)
#pragma unroll
            for (int j = 0; j < 8; j++)
#pragma unroll
                for (int r = 0; r < 4; r++) {
                    int b = (pb << 5) + 16 * s + 8 * (r >> 1) + gid;
                    int c = (pd << 6) + 8 * j + 2 * tg + (r & 1);
                    atomicAdd(&out[b * 128 + c], pc[s][j][r]);
                }
    }
}

extern "C" void kernel_launch(void* const* d_in, const int* in_sizes, int n_in,
                              void* d_out, int out_size) {
    (void)in_sizes; (void)n_in; (void)out_size;
    cudaFuncSetAttribute(agg_kernel, cudaFuncAttributeMaxDynamicSharedMemorySize, SMEM_BYTES);
    zero_out_kernel<<<32, 512>>>((float*)d_out);
    agg_kernel<<<148, THREADS, SMEM_BYTES>>>(
        (const float*)d_in[0], (const int*)d_in[1], (const float*)d_in[2],
        (const float*)d_in[3], (const float*)d_in[4], (const float*)d_in[5], (float*)d_out);
}

// round 7
// speedup vs baseline: 1.0961x; 1.0961x over previous
#include <cuda_runtime.h>
#include <cstdint>

#define NTOT 500000
#define CT 64
#define THREADS 512
#define NTILES ((NTOT + CT - 1) / CT)   // 7813

// smem layout (float offsets)
#define OFF_WT 0        // [128 k][128 n], n ^ ((k&3)<<3)
#define OFF_WG 16384
#define OFF_X  32768    // [64 m][128 k], k ^ ((m&7)<<2)
#define OFF_M  40960    // [128 b][64 k] int, k ^ ((b&7)<<2)
#define OFF_Y  49152    // [64 m][128 n], n ^ (((m&3)<<3)|((m&4)>>2))
#define SMEM_FLOATS 57344
#define SMEM_BYTES (SMEM_FLOATS * 4)    // 229376 <= 232448

__device__ __forceinline__ float cvt_tf32_f(float x) {
    uint32_t u; asm("cvt.rna.tf32.f32 %0, %1;" : "=r"(u) : "f"(x));
    return __uint_as_float(u);
}
__device__ __forceinline__ void mma8(float* c,
                                     uint32_t a0, uint32_t a1, uint32_t a2, uint32_t a3,
                                     uint32_t b0, uint32_t b1) {
    asm volatile(
        "mma.sync.aligned.m16n8k8.row.col.f32.tf32.tf32.f32 "
        "{%0,%1,%2,%3}, {%4,%5,%6,%7}, {%8,%9}, {%0,%1,%2,%3};"
        : "+f"(c[0]), "+f"(c[1]), "+f"(c[2]), "+f"(c[3])
        : "r"(a0), "r"(a1), "r"(a2), "r"(a3), "r"(b0), "r"(b1));
}
__device__ __forceinline__ void cp16(uint32_t saddr, const void* g, int szbytes) {
    asm volatile("cp.async.cg.shared.global [%0], [%1], 16, %2;"
                 :: "r"(saddr), "l"(g), "r"(szbytes));
}
#define CP_COMMIT() asm volatile("cp.async.commit_group;")
#define CP_WAIT0()  asm volatile("cp.async.wait_group 0;")

extern "C" __global__ void zero_out_kernel(float* __restrict__ out) {
    int i = blockIdx.x * blockDim.x + threadIdx.x;
    if (i < 128 * 128) out[i] = 0.0f;
}

// ---- phase A k-step: 8 X-LDS + 8 W-LDS -> 8 MMAs ----
#define ASTEP(ks) do {                                                          \
    const int k0 = (ks) * 8 + tg;                                               \
    const int r0 = (mbase + gid) << 7;                                          \
    uint32_t a0 = __float_as_uint(sX[r0 + (k0 ^ xsw)]);                         \
    uint32_t a1 = __float_as_uint(sX[r0 + (8 << 7) + (k0 ^ xsw)]);              \
    uint32_t a2 = __float_as_uint(sX[r0 + ((k0 + 4) ^ xsw)]);                   \
    uint32_t a3 = __float_as_uint(sX[r0 + (8 << 7) + ((k0 + 4) ^ xsw)]);        \
    uint32_t a4 = __float_as_uint(sX[r0 + (16 << 7) + (k0 ^ xsw)]);             \
    uint32_t a5 = __float_as_uint(sX[r0 + (24 << 7) + (k0 ^ xsw)]);             \
    uint32_t a6 = __float_as_uint(sX[r0 + (16 << 7) + ((k0 + 4) ^ xsw)]);       \
    uint32_t a7 = __float_as_uint(sX[r0 + (24 << 7) + ((k0 + 4) ^ xsw)]);       \
    const int base0 = k0 << 7;                                                  \
    const int base1 = (k0 + 4) << 7;                                            \
    _Pragma("unroll")                                                           \
    for (int j = 0; j < 2; j++) {                                               \
        const int cidx = (nb + 8 * j + gid) ^ (tg << 3);                        \
        uint32_t d0 = __float_as_uint(sWt[base0 + cidx]);                       \
        uint32_t d1 = __float_as_uint(sWt[base1 + cidx]);                       \
        mma8(aD[0][j], a0, a1, a2, a3, d0, d1);                                 \
        mma8(aD[1][j], a4, a5, a6, a7, d0, d1);                                 \
        uint32_t g0 = __float_as_uint(sWg[base0 + cidx]);                       \
        uint32_t g1 = __float_as_uint(sWg[base1 + cidx]);                       \
        mma8(aG[0][j], a0, a1, a2, a3, g0, g1);                                 \
        mma8(aG[1][j], a4, a5, a6, a7, g0, g1);                                 \
    }                                                                           \
} while (0)

// ---- phase B k-step: 8 M-LDS + 8 Y-LDS -> 8 MMAs ----
#define BSTEP(ks) do {                                                          \
    const int kk = (ks) * 8 + tg;                                               \
    uint32_t m0 = __float_as_uint((float)sM[(brow0 << 6)        + (kk ^ msw)]); \
    uint32_t m1 = __float_as_uint((float)sM[((brow0 + 8) << 6)  + (kk ^ msw)]); \
    uint32_t m2 = __float_as_uint((float)sM[(brow0 << 6)        + ((kk + 4) ^ msw)]); \
    uint32_t m3 = __float_as_uint((float)sM[((brow0 + 8) << 6)  + ((kk + 4) ^ msw)]); \
    uint32_t m4 = __float_as_uint((float)sM[((brow0 + 16) << 6) + (kk ^ msw)]); \
    uint32_t m5 = __float_as_uint((float)sM[((brow0 + 24) << 6) + (kk ^ msw)]); \
    uint32_t m6 = __float_as_uint((float)sM[((brow0 + 16) << 6) + ((kk + 4) ^ msw)]); \
    uint32_t m7 = __float_as_uint((float)sM[((brow0 + 24) << 6) + ((kk + 4) ^ msw)]); \
    const int yb0 = kk << 7;                                                    \
    const int yb1 = (kk + 4) << 7;                                              \
    const int ysw0 = tg << 3;                                                   \
    const int ysw1 = (tg << 3) | 1;                                             \
    _Pragma("unroll")                                                           \
    for (int j = 0; j < 4; j++) {                                               \
        const int d = (pd << 5) + 8 * j + gid;                                  \
        uint32_t y0 = __float_as_uint(sY[yb0 + (d ^ ysw0)]);                    \
        uint32_t y1 = __float_as_uint(sY[yb1 + (d ^ ysw1)]);                    \
        mma8(pc[0][j], m0, m1, m2, m3, y0, y1);                                 \
        mma8(pc[1][j], m4, m5, m6, m7, y0, y1);                                 \
    }                                                                           \
} while (0)

#define ISSUE_X(tile) do {                                                      \
    const int nn0 = (tile) * CT;                                                \
    _Pragma("unroll")                                                           \
    for (int p = 0; p < 4; p++) {                                               \
        int id = tid + THREADS * p;                                             \
        int row = id >> 5, ch = id & 31;                                        \
        int n = nn0 + row;                                                      \
        cp16(sx_u32 + (((row << 7) + ((ch ^ (row & 7)) << 2)) << 2),            \
             nodes + (size_t)(n < NTOT ? n : 0) * 128 + ch * 4,                 \
             n < NTOT ? 16 : 0);                                                \
    }                                                                           \
} while (0)

#define ISSUE_M(tile) do {                                                      \
    const int nn0 = (tile) * CT;                                                \
    _Pragma("unroll")                                                           \
    for (int p = 0; p < 4; p++) {                                               \
        int id = tid + THREADS * p;                                             \
        int b = id >> 4, ch = id & 15;                                          \
        int ok = (nn0 + ch * 4) < NTOT;                                         \
        cp16(sm_u32 + (((b << 6) + ((ch ^ (b & 7)) << 2)) << 2),                \
             masks + (size_t)b * NTOT + (ok ? nn0 + ch * 4 : 0), ok ? 16 : 0);  \
    }                                                                           \
} while (0)

#define EPILOGUE() do {                                                         \
    _Pragma("unroll")                                                           \
    for (int s = 0; s < 2; s++)                                                 \
    _Pragma("unroll")                                                           \
    for (int j = 0; j < 2; j++)                                                 \
    _Pragma("unroll")                                                           \
    for (int r = 0; r < 4; r++) {                                               \
        int r1 = r & 1, r2 = r >> 1;                                            \
        int m = mbase + 16 * s + 8 * r2 + gid;                                  \
        int n = nb + 8 * j + 2 * tg + r1;                                       \
        float d  = aD[s][j][r] + btv[j][r1];                                    \
        float gl = aG[s][j][r] + bgv[j][r1];                                    \
        float y = d / (1.0f + __expf(-gl));                                     \
        sY[(m << 7) + (n ^ swc)] = cvt_tf32_f(y);                               \
    }                                                                           \
} while (0)

extern "C" __global__ void __launch_bounds__(THREADS, 1)
agg_kernel(const float* __restrict__ nodes, const int* __restrict__ masks,
           const float* __restrict__ Wt, const float* __restrict__ bt,
           const float* __restrict__ Wg, const float* __restrict__ bg,
           float* __restrict__ out) {
    extern __shared__ float sm[];
    float* sWt = sm + OFF_WT;
    float* sWg = sm + OFF_WG;
    float* sX  = sm + OFF_X;
    int*   sM  = (int*)(sm + OFF_M);
    float* sY  = sm + OFF_Y;

    const uint32_t smem_u32 = (uint32_t)__cvta_generic_to_shared(sm);
    const uint32_t sx_u32 = smem_u32 + OFF_X * 4;
    const uint32_t sm_u32 = smem_u32 + OFF_M * 4;

    const int tid  = threadIdx.x;
    const int warp = tid >> 5;
    const int lane = tid & 31;
    const int tg   = lane & 3;
    const int gid  = lane >> 2;
    const int stride = gridDim.x;

    // phase A mapping: 32m x 16n per warp
    const int mbase = (warp & 1) << 5;
    const int nb    = (warp >> 1) << 4;
    // phase B mapping: 32b x 32d per warp
    const int pb = warp & 3;
    const int pd = warp >> 2;
    const int brow0 = (pb << 5) + gid;
    const int xsw = gid << 2;
    const int msw = gid << 2;
    const int swc = ((gid & 3) << 3) | ((gid & 4) >> 2);

    int t = blockIdx.x;          // always < NTILES (148 <= 7813)

    // prologue: start X(t) streaming before anything else
    ISSUE_X(t);
    CP_COMMIT();

    // W + bias (once); W pre-rounded rna
    for (int i = tid; i < 128 * 128; i += THREADS) {
        int k = i >> 7, n = i & 127;
        int idx = (k << 7) + (n ^ ((k & 3) << 3));
        sWt[idx] = cvt_tf32_f(Wt[i]);
        sWg[idx] = cvt_tf32_f(Wg[i]);
    }
    float btv[2][2], bgv[2][2];
#pragma unroll
    for (int j = 0; j < 2; j++)
#pragma unroll
        for (int r1 = 0; r1 < 2; r1++) {
            int n = nb + 8 * j + 2 * tg + r1;
            btv[j][r1] = bt[n];
            bgv[j][r1] = bg[n];
        }

    float pc[2][4][4];
#pragma unroll
    for (int s = 0; s < 2; s++)
#pragma unroll
        for (int j = 0; j < 4; j++)
#pragma unroll
            for (int r = 0; r < 4; r++) pc[s][j][r] = 0.0f;

    float aD[2][2][4], aG[2][2][4];

    // ================= peeled first tile: GEMM only =================
    {
        CP_WAIT0();
        __syncthreads();     // X(t) + W visible
#pragma unroll
        for (int s = 0; s < 2; s++)
#pragma unroll
            for (int j = 0; j < 2; j++)
#pragma unroll
                for (int r = 0; r < 4; r++) { aD[s][j][r] = 0.0f; aG[s][j][r] = 0.0f; }
#pragma unroll 4
        for (int ks = 0; ks < 16; ks++) ASTEP(ks);
        __syncthreads();     // all done reading sX
        if (t + stride < NTILES) ISSUE_X(t + stride);
        ISSUE_M(t);
        CP_COMMIT();
        EPILOGUE();          // writes Y(t)
        t += stride;
    }

    // ================= fused main loop: GEMM(t) + pool(t-1) =================
    for (; t < NTILES; t += stride) {
        CP_WAIT0();          // X(t), M(t-1) landed
        __syncthreads();     // + Y(t-1) visible
#pragma unroll
        for (int s = 0; s < 2; s++)
#pragma unroll
            for (int j = 0; j < 2; j++)
#pragma unroll
                for (int r = 0; r < 4; r++) { aD[s][j][r] = 0.0f; aG[s][j][r] = 0.0f; }
#pragma unroll 2
        for (int k8 = 0; k8 < 8; k8++) {
            ASTEP(2 * k8);
            ASTEP(2 * k8 + 1);
            BSTEP(k8);
        }
        __syncthreads();     // all done reading sX, sM, sY
        if (t + stride < NTILES) ISSUE_X(t + stride);
        ISSUE_M(t);
        CP_COMMIT();
        EPILOGUE();          // writes Y(t)
    }

    // ================= drain: pool for the last processed tile =================
    CP_WAIT0();
    __syncthreads();         // M(last) + Y(last) visible
#pragma unroll 4
    for (int ks = 0; ks < 8; ks++) BSTEP(ks);

    // final reduction: one atomicAdd per pooled element per CTA
#pragma unroll
    for (int s = 0; s < 2; s++)
#pragma unroll
        for (int j = 0; j < 4; j++)
#pragma unroll
            for (int r = 0; r < 4; r++) {
                int b = (pb << 5) + 16 * s + 8 * (r >> 1) + gid;
                int c = (pd << 5) + 8 * j + 2 * tg + (r & 1);
                atomicAdd(&out[b * 128 + c], pc[s][j][r]);
            }
}

extern "C" void kernel_launch(void* const* d_in, const int* in_sizes, int n_in,
                              void* d_out, int out_size) {
    (void)in_sizes; (void)n_in; (void)out_size;
    cudaFuncSetAttribute(agg_kernel, cudaFuncAttributeMaxDynamicSharedMemorySize, SMEM_BYTES);
    zero_out_kernel<<<32, 512>>>((float*)d_out);
    agg_kernel<<<148, THREADS, SMEM_BYTES>>>(
        (const float*)d_in[0], (const int*)d_in[1], (const float*)d_in[2],
        (const float*)d_in[3], (const float*)d_in[4], (const float*)d_in[5], (float*)d_out);
}